// round 15
// baseline (speedup 1.0000x reference)
#include <cuda_runtime.h>
#include <cuda_fp16.h>
#include <mma.h>
using namespace nvcuda;

#define NN 100000
#define EE 1600000
#define TPB 256

static inline int cdiv(long long a, int b) { return (int)((a + b - 1) / b); }

// ---------------- device scratch ----------------
// packed per-node row (72 floats): [0..19]=feat as 40 half | [20..23]=asrc | [24..27]=adst | [28..67]=skip | pad
__device__ __align__(16) float g_xwp[(size_t)NN * 72];
__device__ __align__(16) float g_h[(size_t)NN * 40];
__device__ __align__(16) __half g_z[(size_t)NN * 288];  // z(240) | h2 skip(40) | zero pad(8)
__device__ float g_asrc[(size_t)NN * 6];
__device__ float g_adst[(size_t)NN * 6];
__device__ int g_cnt[NN], g_ptr[NN], g_cur[NN], g_bsum[128];
__device__ int g_csrc[EE];
__device__ float g_w1e[50 * 88];
__device__ float g_w2e[40 * 88];
__device__ __align__(16) __half g_w3h[288 * 128];
__device__ float g_bc1[40], g_bc2[40], g_bc3[121];
__device__ float g_vs3[240], g_vd3[240];

__device__ __forceinline__ float lrelu(float x) { return x > 0.f ? x : 0.2f * x; }

// ---------------- weight repack ----------------
__global__ void k_repack12(const float* __restrict__ W, const float* __restrict__ lw,
                           const float* __restrict__ as_, const float* __restrict__ ad_,
                           const float* __restrict__ b, const float* __restrict__ lb,
                           float* we, float* bc, int K) {
    int t = blockIdx.x * blockDim.x + threadIdx.x;
    if (t >= K * 88) return;
    int k = t / 88, j = t % 88;
    float v;
    if (j < 40) v = W[k * 40 + j];
    else if (j < 80) v = lw[k * 40 + (j - 40)];
    else if (j < 84) {
        int h = j - 80; float a = 0.f;
        for (int d = 0; d < 10; d++) a += W[k * 40 + h * 10 + d] * as_[h * 10 + d];
        v = a;
    } else {
        int h = j - 84; float a = 0.f;
        for (int d = 0; d < 10; d++) a += W[k * 40 + h * 10 + d] * ad_[h * 10 + d];
        v = a;
    }
    we[t] = v;
    if (k == 0 && j < 40) bc[j] = b[j] + lb[j];
}

__global__ void k_repack3h(const float* __restrict__ W3, const float* __restrict__ lw3,
                           const float* __restrict__ b3, const float* __restrict__ lb3,
                           __half* wh, float* bc) {
    int t = blockIdx.x * blockDim.x + threadIdx.x;
    if (t >= 288 * 128) return;
    int r = t >> 7, c = t & 127;
    float v = 0.f;
    if (c < 121) {
        if (r < 240) { int h = r / 40, k = r % 40; v = W3[k * 726 + h * 121 + c]; }
        else if (r < 280) v = lw3[(r - 240) * 121 + c];
    }
    wh[t] = __float2half(v);
    if (r == 0 && c < 121) bc[c] = b3[c] + lb3[c];
}

__global__ void k_vsd3(const float* __restrict__ W3, const float* __restrict__ as3,
                       const float* __restrict__ ad3, float* vs, float* vd) {
    int w = (blockIdx.x * blockDim.x + threadIdx.x) >> 5;
    int lane = threadIdx.x & 31;
    if (w >= 480) return;
    int side = w / 240, idx = w % 240, h = idx / 40, k = idx % 40;
    const float* att = side ? ad3 : as3;
    float a = 0.f;
    for (int c = lane; c < 121; c += 32) a += W3[k * 726 + h * 121 + c] * att[h * 121 + c];
#pragma unroll
    for (int o = 16; o; o >>= 1) a += __shfl_down_sync(0xffffffffu, a, o);
    if (lane == 0) (side ? vd : vs)[idx] = a;
}

// ---------------- CSR build ----------------
__global__ void k_hist(const int* __restrict__ dst, int* cnt, int E) {
    int t = blockIdx.x * blockDim.x + threadIdx.x;
    if (t < E) atomicAdd(&cnt[dst[t]], 1);
}

__global__ void k_scan1(const int* __restrict__ cnt, int* ptr, int* bsum, int n) {
    __shared__ int sh[1024];
    int i = blockIdx.x * 1024 + threadIdx.x;
    int v = (i < n) ? cnt[i] : 0;
    sh[threadIdx.x] = v;
    __syncthreads();
    for (int off = 1; off < 1024; off <<= 1) {
        int t = (threadIdx.x >= off) ? sh[threadIdx.x - off] : 0;
        __syncthreads();
        sh[threadIdx.x] += t;
        __syncthreads();
    }
    if (i < n) ptr[i] = sh[threadIdx.x] - v;
    if (threadIdx.x == 1023) bsum[blockIdx.x] = sh[1023];
}

__global__ void k_scan2(int* bsum, int nb) {
    __shared__ int sh[128];
    int v = (threadIdx.x < nb) ? bsum[threadIdx.x] : 0;
    sh[threadIdx.x] = v;
    __syncthreads();
    for (int off = 1; off < 128; off <<= 1) {
        int t = (threadIdx.x >= off) ? sh[threadIdx.x - off] : 0;
        __syncthreads();
        sh[threadIdx.x] += t;
        __syncthreads();
    }
    if (threadIdx.x < nb) bsum[threadIdx.x] = sh[threadIdx.x] - v;
}

__global__ void k_scan3(int* ptr, int* cur, const int* __restrict__ bsum, int n) {
    int i = blockIdx.x * blockDim.x + threadIdx.x;
    if (i >= n) return;
    int p = ptr[i] + bsum[i >> 10];
    ptr[i] = p;
    cur[i] = p;
}

__global__ void k_scatter(const int* __restrict__ src, const int* __restrict__ dst,
                          int* cur, int* csrc, int E) {
    int t = blockIdx.x * blockDim.x + threadIdx.x;
    if (t >= E) return;
    int slot = atomicAdd(&cur[dst[t]], 1);
    csrc[slot] = src[t];
}

// ---------------- SIMT fp32 GEMM 64x96, epilogue writes packed row ----------------
__global__ __launch_bounds__(256) void k_gemm96p(const float* __restrict__ A, int lda,
                                                 const float* __restrict__ B,
                                                 float* __restrict__ X,   // packed rows, stride 72
                                                 int M, int K) {
    const int NC = 88;
    __shared__ __align__(16) float As[16][68];
    __shared__ __align__(16) float Bs[16][100];
    int bm = blockIdx.x * 64;
    int tid = threadIdx.x;
    int tx = tid & 15, ty = tid >> 4;
    float acc[4][6] = {};
    for (int k0 = 0; k0 < K; k0 += 16) {
        for (int i = tid; i < 64 * 16; i += 256) {
            int m = i >> 4, kk = i & 15;
            int gm = bm + m, gk = k0 + kk;
            As[kk][m] = (gm < M && gk < K) ? A[(long long)gm * lda + gk] : 0.f;
        }
        for (int i = tid; i < 16 * 96; i += 256) {
            int kk = i / 96, nn = i - kk * 96;
            int gk = k0 + kk;
            Bs[kk][nn] = (gk < K && nn < NC) ? B[gk * NC + nn] : 0.f;
        }
        __syncthreads();
#pragma unroll
        for (int kk = 0; kk < 16; kk++) {
            float a[4], b[6];
#pragma unroll
            for (int i = 0; i < 4; i++) a[i] = As[kk][ty * 4 + i];
#pragma unroll
            for (int j = 0; j < 6; j++) b[j] = Bs[kk][tx * 6 + j];
#pragma unroll
            for (int i = 0; i < 4; i++)
#pragma unroll
                for (int j = 0; j < 6; j++) acc[i][j] += a[i] * b[j];
        }
        __syncthreads();
    }
#pragma unroll
    for (int i = 0; i < 4; i++) {
        int r = bm + ty * 4 + i;
        if (r >= M) continue;
        float* rowf = X + (long long)r * 72;
        __half* rowh = (__half*)rowf;
#pragma unroll
        for (int j = 0; j < 6; j++) {
            int cc = tx * 6 + j;
            if (cc >= NC) continue;
            float v = acc[i][j];
            if (cc < 40) rowh[cc] = __float2half(v);
            else if (cc < 80) rowf[28 + cc - 40] = v;
            else if (cc < 84) rowf[20 + cc - 80] = v;
            else rowf[24 + cc - 84] = v;
        }
    }
}

// ---------------- fp16 tensor-core GEMM (layer 3 output), A already half ----------------
__global__ __launch_bounds__(256) void k_gemm_h16(
    const __half* __restrict__ Ah, const __half* __restrict__ Bh,
    float* __restrict__ C, int ldc, int M,
    const float* __restrict__ bias) {
    __shared__ __align__(16) __half As[128][40];
    __shared__ __align__(16) __half Bs[32][136];
    __shared__ __align__(16) float stg[8][16][20];
    int bm = blockIdx.x * 128;
    int tid = threadIdx.x;
    int wid = tid >> 5, lane = tid & 31;
    int wm = wid >> 1, wn = wid & 1;

    wmma::fragment<wmma::accumulator, 16, 16, 16, float> acc[2][4];
#pragma unroll
    for (int i = 0; i < 2; i++)
#pragma unroll
        for (int j = 0; j < 4; j++) wmma::fill_fragment(acc[i][j], 0.f);

    for (int k0 = 0; k0 < 288; k0 += 32) {
#pragma unroll
        for (int i = tid; i < 128 * 4; i += 256) {
            int m = i >> 2, q = i & 3;
            int gm = bm + m;
            uint4 v = make_uint4(0, 0, 0, 0);
            if (gm < M) v = *(const uint4*)(Ah + (long long)gm * 288 + k0 + q * 8);
            *(uint4*)&As[m][q * 8] = v;
        }
#pragma unroll
        for (int i = tid; i < 32 * 128; i += 256) {
            int kk = i >> 7, nn = i & 127;
            Bs[kk][nn] = Bh[(k0 + kk) * 128 + nn];
        }
        __syncthreads();
#pragma unroll
        for (int ks = 0; ks < 32; ks += 16) {
            wmma::fragment<wmma::matrix_a, 16, 16, 16, __half, wmma::row_major> fa[2];
            wmma::load_matrix_sync(fa[0], &As[wm * 32][ks], 40);
            wmma::load_matrix_sync(fa[1], &As[wm * 32 + 16][ks], 40);
#pragma unroll
            for (int j = 0; j < 4; j++) {
                wmma::fragment<wmma::matrix_b, 16, 16, 16, __half, wmma::row_major> fb;
                wmma::load_matrix_sync(fb, &Bs[ks][wn * 64 + j * 16], 136);
                wmma::mma_sync(acc[0][j], fa[0], fb, acc[0][j]);
                wmma::mma_sync(acc[1][j], fa[1], fb, acc[1][j]);
            }
        }
        __syncthreads();
    }
#pragma unroll
    for (int i = 0; i < 2; i++)
#pragma unroll
        for (int j = 0; j < 4; j++) {
            wmma::store_matrix_sync(&stg[wid][0][0], acc[i][j], 20, wmma::mem_row_major);
            __syncwarp();
            int rb = bm + wm * 32 + i * 16;
            int cb = wn * 64 + j * 16;
            for (int t = lane; t < 256; t += 32) {
                int r = t >> 4, c = t & 15;
                int gr = rb + r, gc = cb + c;
                if (gr < M && gc < 121)
                    C[(long long)gr * ldc + gc] = stg[wid][r][c] + bias[gc];
            }
            __syncwarp();
        }
}

// ---------------- warp-per-node aggregation, layers 1/2 ----------------
// One warp owns one destination node: uniform loop bound (zero divergence),
// coalesced 80B feature loads, broadcast logit loads, weights via shfl.
__global__ __launch_bounds__(256) void k_agg12w(
    const int* __restrict__ ptr, const int* __restrict__ cnt,
    const int* __restrict__ csrc, const float* __restrict__ X,
    const float* __restrict__ bias,
    float* __restrict__ hout, __half* __restrict__ zout, int n) {
    int node = (blockIdx.x * blockDim.x + threadIdx.x) >> 5;
    if (node >= n) return;
    int lane = threadIdx.x & 31;
    int h4 = lane & 3;                 // head whose weight this lane computes
    int hl = lane / 5; if (hl > 3) hl = 3;  // head owning this lane's feature pair (l<20)
    int fidx = (lane < 20) ? lane : 0;

    const float* rowf = X + (long long)node * 72;
    float adv = rowf[24 + h4];
    float ws = __expf(lrelu(rowf[20 + h4] + adv));   // self weight, head h4 (all lanes)
    float den = ws;
    float2 fs = __half22float2(((const __half2*)rowf)[fidx]);
    float wself = __shfl_sync(0xffffffffu, ws, hl);
    float accx = fs.x * wself, accy = fs.y * wself;

    int st = ptr[node], deg = cnt[node];
    int sidx = 0;
    for (int k = 0; k < deg; k++) {
        if ((k & 31) == 0)
            sidx = (k + lane < deg) ? csrc[st + k + lane] : 0;
        int s = __shfl_sync(0xffffffffu, sidx, k & 31);
        const float* rows = X + (long long)s * 72;
        float w = __expf(lrelu(rows[20 + h4] + adv));
        den += w;
        float wl = __shfl_sync(0xffffffffu, w, hl);
        float2 f = __half22float2(((const __half2*)rows)[fidx]);
        accx += f.x * wl;
        accy += f.y * wl;
    }
    float dl = __shfl_sync(0xffffffffu, den, hl);
    if (lane < 20) {
        float inv = 1.f / dl;
        int c = lane * 2;
        float vx = accx * inv + rowf[28 + c]     + bias[c];
        float vy = accy * inv + rowf[28 + c + 1] + bias[c + 1];
        vx = vx > 0.f ? vx : (__expf(vx) - 1.f);
        vy = vy > 0.f ? vy : (__expf(vy) - 1.f);
        ((float2*)(hout + (long long)node * 40))[lane] = make_float2(vx, vy);
        if (zout)
            ((__half2*)(zout + (long long)node * 288 + 240))[lane] = __floats2half2_rn(vx, vy);
    }
}

// ---------------- layer 3 ----------------
// per-node attention logits (both sides)
__global__ void k_att3(const float* __restrict__ h2, const float* __restrict__ vs,
                       const float* __restrict__ vd, float* as_, float* ad_, int n) {
    int t = blockIdx.x * blockDim.x + threadIdx.x;
    if (t >= n * 6) return;
    int node = t / 6, h = t - node * 6;
    const float* hr = &h2[(long long)node * 40];
    const float* v1 = &vs[h * 40];
    const float* v2 = &vd[h * 40];
    float a = 0.f, b = 0.f;
#pragma unroll
    for (int k = 0; k < 40; k++) { float x = hr[k]; a += x * v1[k]; b += x * v2[k]; }
    as_[t] = a;
    ad_[t] = b;
}

// warp-per-node layer-3 aggregation: one 80B gather serves all 6 heads.
__global__ __launch_bounds__(256) void k_agg3w(
    const int* __restrict__ ptr, const int* __restrict__ cnt,
    const int* __restrict__ csrc, const float* __restrict__ h2,
    const float* __restrict__ as_, const float* __restrict__ ad_,
    __half* __restrict__ z, int n) {
    int node = (blockIdx.x * blockDim.x + threadIdx.x) >> 5;
    if (node >= n) return;
    int lane = threadIdx.x & 31;
    int h6 = lane % 6;
    int fidx = (lane < 20) ? lane : 0;

    float adv = ad_[node * 6 + h6];
    float ws = __expf(lrelu(as_[node * 6 + h6] + adv));
    float den = ws;
    float2 fs = ((const float2*)(h2 + (long long)node * 40))[fidx];
    float ax[6], ay[6];
#pragma unroll
    for (int h = 0; h < 6; h++) {
        float w = __shfl_sync(0xffffffffu, ws, h);
        ax[h] = fs.x * w;
        ay[h] = fs.y * w;
    }
    int st = ptr[node], deg = cnt[node];
    int sidx = 0;
    for (int k = 0; k < deg; k++) {
        if ((k & 31) == 0)
            sidx = (k + lane < deg) ? csrc[st + k + lane] : 0;
        int s = __shfl_sync(0xffffffffu, sidx, k & 31);
        float w = __expf(lrelu(as_[s * 6 + h6] + adv));
        den += w;
        float2 f = __half22float2(((const __half2*)(z + (long long)s * 288 + 240))[fidx]);
#pragma unroll
        for (int h = 0; h < 6; h++) {
            float wh = __shfl_sync(0xffffffffu, w, h);
            ax[h] += f.x * wh;
            ay[h] += f.y * wh;
        }
    }
    float sc[6];
#pragma unroll
    for (int h = 0; h < 6; h++)
        sc[h] = 1.f / (6.f * __shfl_sync(0xffffffffu, den, h));
    if (lane < 20) {
        long long base = (long long)node * 288;
#pragma unroll
        for (int h = 0; h < 6; h++)
            ((__half2*)(z + base + h * 40))[lane] =
                __floats2half2_rn(ax[h] * sc[h], ay[h] * sc[h]);
    }
}

// ---------------- host ----------------
extern "C" void kernel_launch(void* const* d_in, const int* in_sizes, int n_in,
                              void* d_out, int out_size) {
    const float* x   = (const float*)d_in[0];
    const int*   ei  = (const int*)d_in[1];
    const float* W1  = (const float*)d_in[2];
    const float* as1 = (const float*)d_in[3];
    const float* ad1 = (const float*)d_in[4];
    const float* b1  = (const float*)d_in[5];
    const float* lw1 = (const float*)d_in[6];
    const float* lb1 = (const float*)d_in[7];
    const float* W2  = (const float*)d_in[8];
    const float* as2 = (const float*)d_in[9];
    const float* ad2 = (const float*)d_in[10];
    const float* b2  = (const float*)d_in[11];
    const float* lw2 = (const float*)d_in[12];
    const float* lb2 = (const float*)d_in[13];
    const float* W3  = (const float*)d_in[14];
    const float* as3 = (const float*)d_in[15];
    const float* ad3 = (const float*)d_in[16];
    const float* b3  = (const float*)d_in[17];
    const float* lw3 = (const float*)d_in[18];
    const float* lb3 = (const float*)d_in[19];
    float* out = (float*)d_out;

    int E = in_sizes[1] / 2;
    int n = in_sizes[0] / 50;
    const int* src = ei;
    const int* dst = ei + E;

    float *xwp, *h, *asrc, *adst;
    float *w1e, *w2e, *bc1, *bc2, *bc3, *vs3, *vd3;
    __half *w3h, *z;
    int *cnt, *ptr, *cur, *bsum, *csrc;
    cudaGetSymbolAddress((void**)&xwp, g_xwp);
    cudaGetSymbolAddress((void**)&h, g_h);
    cudaGetSymbolAddress((void**)&z, g_z);
    cudaGetSymbolAddress((void**)&asrc, g_asrc);
    cudaGetSymbolAddress((void**)&adst, g_adst);
    cudaGetSymbolAddress((void**)&cnt, g_cnt);
    cudaGetSymbolAddress((void**)&ptr, g_ptr);
    cudaGetSymbolAddress((void**)&cur, g_cur);
    cudaGetSymbolAddress((void**)&bsum, g_bsum);
    cudaGetSymbolAddress((void**)&csrc, g_csrc);
    cudaGetSymbolAddress((void**)&w1e, g_w1e);
    cudaGetSymbolAddress((void**)&w2e, g_w2e);
    cudaGetSymbolAddress((void**)&w3h, g_w3h);
    cudaGetSymbolAddress((void**)&bc1, g_bc1);
    cudaGetSymbolAddress((void**)&bc2, g_bc2);
    cudaGetSymbolAddress((void**)&bc3, g_bc3);
    cudaGetSymbolAddress((void**)&vs3, g_vs3);
    cudaGetSymbolAddress((void**)&vd3, g_vd3);

    // z zero-init (pad cols 280..287 must be zero for the padded GEMM)
    cudaMemsetAsync(z, 0, (size_t)NN * 288 * sizeof(__half));

    // weight repack
    k_repack12<<<cdiv(50 * 88, TPB), TPB>>>(W1, lw1, as1, ad1, b1, lb1, w1e, bc1, 50);
    k_repack12<<<cdiv(40 * 88, TPB), TPB>>>(W2, lw2, as2, ad2, b2, lb2, w2e, bc2, 40);
    k_repack3h<<<cdiv(288 * 128, TPB), TPB>>>(W3, lw3, b3, lb3, w3h, bc3);
    k_vsd3<<<60, TPB>>>(W3, as3, ad3, vs3, vd3);

    // CSR build (shared by all 3 layers)
    cudaMemsetAsync(cnt, 0, (size_t)n * sizeof(int));
    k_hist<<<cdiv(E, TPB), TPB>>>(dst, cnt, E);
    int nb = cdiv(n, 1024);
    k_scan1<<<nb, 1024>>>(cnt, ptr, bsum, n);
    k_scan2<<<1, 128>>>(bsum, nb);
    k_scan3<<<cdiv(n, TPB), TPB>>>(ptr, cur, bsum, n);
    k_scatter<<<cdiv(E, TPB), TPB>>>(src, dst, cur, csrc, E);

    // ---- layer 1 ----
    k_gemm96p<<<cdiv(n, 64), 256>>>(x, 50, w1e, xwp, n, 50);
    k_agg12w<<<cdiv((long long)n * 32, TPB), TPB>>>(ptr, cnt, csrc, xwp, bc1, h, nullptr, n);

    // ---- layer 2 ----
    k_gemm96p<<<cdiv(n, 64), 256>>>(h, 40, w2e, xwp, n, 40);
    k_agg12w<<<cdiv((long long)n * 32, TPB), TPB>>>(ptr, cnt, csrc, xwp, bc2, h, z, n);

    // ---- layer 3 ----
    k_att3<<<cdiv(n * 6, TPB), TPB>>>(h, vs3, vd3, asrc, adst, n);
    k_agg3w<<<cdiv((long long)n * 32, TPB), TPB>>>(ptr, cnt, csrc, h, asrc, adst, z, n);
    k_gemm_h16<<<cdiv(n, 128), 256>>>(z, w3h, out, 121, n, bc3);
}

// round 16
// speedup vs baseline: 1.2381x; 1.2381x over previous
#include <cuda_runtime.h>
#include <cuda_fp16.h>
#include <mma.h>
using namespace nvcuda;

#define NN 100000
#define EE 1600000
#define TPB 256

static inline int cdiv(long long a, int b) { return (int)((a + b - 1) / b); }

// ---------------- device scratch ----------------
// packed per-node row (72 floats): [0..19]=feat as 40 half | [20..23]=asrc | [24..27]=adst | [28..67]=skip | pad
__device__ __align__(16) float g_xwp[(size_t)NN * 72];
__device__ __align__(16) float g_h[(size_t)NN * 40];
__device__ __align__(16) __half g_z[(size_t)NN * 288];  // z(240) | h2 skip(40) | zero pad(8)
__device__ float g_asrc[(size_t)NN * 6];
__device__ float g_adst[(size_t)NN * 6];
__device__ float g_ew[(size_t)EE * 6];
__device__ int g_cnt[NN], g_ptr[NN], g_cur[NN], g_bsum[128];
__device__ int g_csrc[EE];
__device__ float g_w1e[50 * 88];
__device__ float g_w2e[40 * 88];
__device__ __align__(16) __half g_w3h[288 * 128];
__device__ float g_bc1[40], g_bc2[40], g_bc3[121];
__device__ float g_vs3[240], g_vd3[240];

__device__ __forceinline__ float lrelu(float x) { return x > 0.f ? x : 0.2f * x; }

// ---------------- weight repack ----------------
__global__ void k_repack12(const float* __restrict__ W, const float* __restrict__ lw,
                           const float* __restrict__ as_, const float* __restrict__ ad_,
                           const float* __restrict__ b, const float* __restrict__ lb,
                           float* we, float* bc, int K) {
    int t = blockIdx.x * blockDim.x + threadIdx.x;
    if (t >= K * 88) return;
    int k = t / 88, j = t % 88;
    float v;
    if (j < 40) v = W[k * 40 + j];
    else if (j < 80) v = lw[k * 40 + (j - 40)];
    else if (j < 84) {
        int h = j - 80; float a = 0.f;
        for (int d = 0; d < 10; d++) a += W[k * 40 + h * 10 + d] * as_[h * 10 + d];
        v = a;
    } else {
        int h = j - 84; float a = 0.f;
        for (int d = 0; d < 10; d++) a += W[k * 40 + h * 10 + d] * ad_[h * 10 + d];
        v = a;
    }
    we[t] = v;
    if (k == 0 && j < 40) bc[j] = b[j] + lb[j];
}

__global__ void k_repack3h(const float* __restrict__ W3, const float* __restrict__ lw3,
                           const float* __restrict__ b3, const float* __restrict__ lb3,
                           __half* wh, float* bc) {
    int t = blockIdx.x * blockDim.x + threadIdx.x;
    if (t >= 288 * 128) return;
    int r = t >> 7, c = t & 127;
    float v = 0.f;
    if (c < 121) {
        if (r < 240) { int h = r / 40, k = r % 40; v = W3[k * 726 + h * 121 + c]; }
        else if (r < 280) v = lw3[(r - 240) * 121 + c];
    }
    wh[t] = __float2half(v);
    if (r == 0 && c < 121) bc[c] = b3[c] + lb3[c];
}

__global__ void k_vsd3(const float* __restrict__ W3, const float* __restrict__ as3,
                       const float* __restrict__ ad3, float* vs, float* vd) {
    int w = (blockIdx.x * blockDim.x + threadIdx.x) >> 5;
    int lane = threadIdx.x & 31;
    if (w >= 480) return;
    int side = w / 240, idx = w % 240, h = idx / 40, k = idx % 40;
    const float* att = side ? ad3 : as3;
    float a = 0.f;
    for (int c = lane; c < 121; c += 32) a += W3[k * 726 + h * 121 + c] * att[h * 121 + c];
#pragma unroll
    for (int o = 16; o; o >>= 1) a += __shfl_down_sync(0xffffffffu, a, o);
    if (lane == 0) (side ? vd : vs)[idx] = a;
}

// ---------------- CSR build ----------------
__global__ void k_hist(const int* __restrict__ dst, int* cnt, int E) {
    int t = blockIdx.x * blockDim.x + threadIdx.x;
    if (t < E) atomicAdd(&cnt[dst[t]], 1);
}

__global__ void k_scan1(const int* __restrict__ cnt, int* ptr, int* bsum, int n) {
    __shared__ int sh[1024];
    int i = blockIdx.x * 1024 + threadIdx.x;
    int v = (i < n) ? cnt[i] : 0;
    sh[threadIdx.x] = v;
    __syncthreads();
    for (int off = 1; off < 1024; off <<= 1) {
        int t = (threadIdx.x >= off) ? sh[threadIdx.x - off] : 0;
        __syncthreads();
        sh[threadIdx.x] += t;
        __syncthreads();
    }
    if (i < n) ptr[i] = sh[threadIdx.x] - v;
    if (threadIdx.x == 1023) bsum[blockIdx.x] = sh[1023];
}

__global__ void k_scan2(int* bsum, int nb) {
    __shared__ int sh[128];
    int v = (threadIdx.x < nb) ? bsum[threadIdx.x] : 0;
    sh[threadIdx.x] = v;
    __syncthreads();
    for (int off = 1; off < 128; off <<= 1) {
        int t = (threadIdx.x >= off) ? sh[threadIdx.x - off] : 0;
        __syncthreads();
        sh[threadIdx.x] += t;
        __syncthreads();
    }
    if (threadIdx.x < nb) bsum[threadIdx.x] = sh[threadIdx.x] - v;
}

__global__ void k_scan3(int* ptr, int* cur, const int* __restrict__ bsum, int n) {
    int i = blockIdx.x * blockDim.x + threadIdx.x;
    if (i >= n) return;
    int p = ptr[i] + bsum[i >> 10];
    ptr[i] = p;
    cur[i] = p;
}

__global__ void k_scatter(const int* __restrict__ src, const int* __restrict__ dst,
                          int* cur, int* csrc, int E) {
    int t = blockIdx.x * blockDim.x + threadIdx.x;
    if (t >= E) return;
    int slot = atomicAdd(&cur[dst[t]], 1);
    csrc[slot] = src[t];
}

// ---------------- SIMT fp32 GEMM 64x96, epilogue writes packed row ----------------
__global__ __launch_bounds__(256) void k_gemm96p(const float* __restrict__ A, int lda,
                                                 const float* __restrict__ B,
                                                 float* __restrict__ X,   // packed rows, stride 72
                                                 int M, int K) {
    const int NC = 88;
    __shared__ __align__(16) float As[16][68];
    __shared__ __align__(16) float Bs[16][100];
    int bm = blockIdx.x * 64;
    int tid = threadIdx.x;
    int tx = tid & 15, ty = tid >> 4;
    float acc[4][6] = {};
    for (int k0 = 0; k0 < K; k0 += 16) {
        for (int i = tid; i < 64 * 16; i += 256) {
            int m = i >> 4, kk = i & 15;
            int gm = bm + m, gk = k0 + kk;
            As[kk][m] = (gm < M && gk < K) ? A[(long long)gm * lda + gk] : 0.f;
        }
        for (int i = tid; i < 16 * 96; i += 256) {
            int kk = i / 96, nn = i - kk * 96;
            int gk = k0 + kk;
            Bs[kk][nn] = (gk < K && nn < NC) ? B[gk * NC + nn] : 0.f;
        }
        __syncthreads();
#pragma unroll
        for (int kk = 0; kk < 16; kk++) {
            float a[4], b[6];
#pragma unroll
            for (int i = 0; i < 4; i++) a[i] = As[kk][ty * 4 + i];
#pragma unroll
            for (int j = 0; j < 6; j++) b[j] = Bs[kk][tx * 6 + j];
#pragma unroll
            for (int i = 0; i < 4; i++)
#pragma unroll
                for (int j = 0; j < 6; j++) acc[i][j] += a[i] * b[j];
        }
        __syncthreads();
    }
#pragma unroll
    for (int i = 0; i < 4; i++) {
        int r = bm + ty * 4 + i;
        if (r >= M) continue;
        float* rowf = X + (long long)r * 72;
        __half* rowh = (__half*)rowf;
#pragma unroll
        for (int j = 0; j < 6; j++) {
            int cc = tx * 6 + j;
            if (cc >= NC) continue;
            float v = acc[i][j];
            if (cc < 40) rowh[cc] = __float2half(v);
            else if (cc < 80) rowf[28 + cc - 40] = v;
            else if (cc < 84) rowf[20 + cc - 80] = v;
            else rowf[24 + cc - 84] = v;
        }
    }
}

// ---------------- fp16 tensor-core GEMM (layer 3 output), A already half ----------------
__global__ __launch_bounds__(256) void k_gemm_h16(
    const __half* __restrict__ Ah, const __half* __restrict__ Bh,
    float* __restrict__ C, int ldc, int M,
    const float* __restrict__ bias) {
    __shared__ __align__(16) __half As[128][40];
    __shared__ __align__(16) __half Bs[32][136];
    __shared__ __align__(16) float stg[8][16][20];
    int bm = blockIdx.x * 128;
    int tid = threadIdx.x;
    int wid = tid >> 5, lane = tid & 31;
    int wm = wid >> 1, wn = wid & 1;

    wmma::fragment<wmma::accumulator, 16, 16, 16, float> acc[2][4];
#pragma unroll
    for (int i = 0; i < 2; i++)
#pragma unroll
        for (int j = 0; j < 4; j++) wmma::fill_fragment(acc[i][j], 0.f);

    for (int k0 = 0; k0 < 288; k0 += 32) {
#pragma unroll
        for (int i = tid; i < 128 * 4; i += 256) {
            int m = i >> 2, q = i & 3;
            int gm = bm + m;
            uint4 v = make_uint4(0, 0, 0, 0);
            if (gm < M) v = *(const uint4*)(Ah + (long long)gm * 288 + k0 + q * 8);
            *(uint4*)&As[m][q * 8] = v;
        }
#pragma unroll
        for (int i = tid; i < 32 * 128; i += 256) {
            int kk = i >> 7, nn = i & 127;
            Bs[kk][nn] = Bh[(k0 + kk) * 128 + nn];
        }
        __syncthreads();
#pragma unroll
        for (int ks = 0; ks < 32; ks += 16) {
            wmma::fragment<wmma::matrix_a, 16, 16, 16, __half, wmma::row_major> fa[2];
            wmma::load_matrix_sync(fa[0], &As[wm * 32][ks], 40);
            wmma::load_matrix_sync(fa[1], &As[wm * 32 + 16][ks], 40);
#pragma unroll
            for (int j = 0; j < 4; j++) {
                wmma::fragment<wmma::matrix_b, 16, 16, 16, __half, wmma::row_major> fb;
                wmma::load_matrix_sync(fb, &Bs[ks][wn * 64 + j * 16], 136);
                wmma::mma_sync(acc[0][j], fa[0], fb, acc[0][j]);
                wmma::mma_sync(acc[1][j], fa[1], fb, acc[1][j]);
            }
        }
        __syncthreads();
    }
#pragma unroll
    for (int i = 0; i < 2; i++)
#pragma unroll
        for (int j = 0; j < 4; j++) {
            wmma::store_matrix_sync(&stg[wid][0][0], acc[i][j], 20, wmma::mem_row_major);
            __syncwarp();
            int rb = bm + wm * 32 + i * 16;
            int cb = wn * 64 + j * 16;
            for (int t = lane; t < 256; t += 32) {
                int r = t >> 4, c = t & 15;
                int gr = rb + r, gc = cb + c;
                if (gr < M && gc < 121)
                    C[(long long)gr * ldc + gc] = stg[wid][r][c] + bias[gc];
            }
            __syncwarp();
        }
}

// ---------------- fused aggregation layers 1/2: thread = (node, head), 2x unroll ----------------
__global__ __launch_bounds__(256) void k_agg12(
    const int* __restrict__ ptr, const int* __restrict__ cnt,
    const int* __restrict__ csrc, const float* __restrict__ X,
    const float* __restrict__ bias,
    float* __restrict__ hout, __half* __restrict__ zout, int n) {
    int t = blockIdx.x * blockDim.x + threadIdx.x;
    if (t >= n * 4) return;
    int node = t >> 2, h = t & 3;
    const float* rowf = X + (long long)node * 72;
    const __half2* rh = (const __half2*)((const __half*)rowf + h * 10);
    float adv = rowf[24 + h];
    float w = __expf(lrelu(rowf[20 + h] + adv));
    float den = w;
    float acc[10];
#pragma unroll
    for (int i = 0; i < 5; i++) {
        float2 f = __half22float2(rh[i]);
        acc[2 * i] = w * f.x;
        acc[2 * i + 1] = w * f.y;
    }

    int st = ptr[node], deg = cnt[node];
    int k = 0;
    for (; k + 2 <= deg; k += 2) {
        int s0 = csrc[st + k], s1 = csrc[st + k + 1];
        const float* r0 = X + (long long)s0 * 72;
        const float* r1 = X + (long long)s1 * 72;
        float w0 = __expf(lrelu(r0[20 + h] + adv));
        float w1 = __expf(lrelu(r1[20 + h] + adv));
        den += w0 + w1;
        const __half2* p0 = (const __half2*)((const __half*)r0 + h * 10);
        const __half2* p1 = (const __half2*)((const __half*)r1 + h * 10);
#pragma unroll
        for (int i = 0; i < 5; i++) {
            float2 f0 = __half22float2(p0[i]);
            float2 f1 = __half22float2(p1[i]);
            acc[2 * i]     += f0.x * w0 + f1.x * w1;
            acc[2 * i + 1] += f0.y * w0 + f1.y * w1;
        }
    }
    if (k < deg) {
        int s = csrc[st + k];
        const float* rows = X + (long long)s * 72;
        float wl = __expf(lrelu(rows[20 + h] + adv));
        den += wl;
        const __half2* rp = (const __half2*)((const __half*)rows + h * 10);
#pragma unroll
        for (int i = 0; i < 5; i++) {
            float2 f = __half22float2(rp[i]);
            acc[2 * i]     += f.x * wl;
            acc[2 * i + 1] += f.y * wl;
        }
    }
    float inv = 1.f / den;
    float out[10];
#pragma unroll
    for (int i = 0; i < 10; i++) {
        float v = acc[i] * inv + rowf[28 + h * 10 + i] + bias[h * 10 + i];
        out[i] = v > 0.f ? v : (__expf(v) - 1.f);
    }
    float2* hp = (float2*)(hout + (long long)node * 40 + h * 10);
#pragma unroll
    for (int i = 0; i < 5; i++) hp[i] = make_float2(out[2 * i], out[2 * i + 1]);
    if (zout) {
        __half2* zp = (__half2*)(zout + (long long)node * 288 + 240 + h * 10);
#pragma unroll
        for (int i = 0; i < 5; i++) zp[i] = __floats2half2_rn(out[2 * i], out[2 * i + 1]);
    }
}

// ---------------- layer 3 ----------------
// per-node attention logits (both sides)
__global__ void k_att3(const float* __restrict__ h2, const float* __restrict__ vs,
                       const float* __restrict__ vd, float* as_, float* ad_, int n) {
    int t = blockIdx.x * blockDim.x + threadIdx.x;
    if (t >= n * 6) return;
    int node = t / 6, h = t - node * 6;
    const float* hr = &h2[(long long)node * 40];
    const float* v1 = &vs[h * 40];
    const float* v2 = &vd[h * 40];
    float a = 0.f, b = 0.f;
#pragma unroll
    for (int k = 0; k < 40; k++) { float x = hr[k]; a += x * v1[k]; b += x * v2[k]; }
    as_[t] = a;
    ad_[t] = b;
}

// per-node edge exp weights (dst implicit)
__global__ void k_exp3(const int* __restrict__ ptr, const int* __restrict__ cnt,
                       const int* __restrict__ csrc,
                       const float* __restrict__ as_, const float* __restrict__ ad_,
                       float* __restrict__ ew, int n) {
    int t = blockIdx.x * blockDim.x + threadIdx.x;
    if (t >= n * 6) return;
    int node = t / 6, h = t - node * 6;
    float ad = ad_[t];
    int st = ptr[node], deg = cnt[node];
    for (int k = 0; k < deg; k++) {
        int slot = st + k;
        int s = csrc[slot];
        ew[(long long)slot * 6 + h] = __expf(lrelu(as_[s * 6 + h] + ad));
    }
}

// aggregation: thread = (node, 4 cols), 6 heads in registers; fp16 gathers, 2x unroll
__global__ __launch_bounds__(256) void k_agg3(
    const int* __restrict__ ptr, const int* __restrict__ cnt,
    const int* __restrict__ csrc, const float* __restrict__ h2,
    const float* __restrict__ ew, const float* __restrict__ as_,
    const float* __restrict__ ad_, __half* __restrict__ z, int n) {
    int t = blockIdx.x * blockDim.x + threadIdx.x;
    if (t >= n * 10) return;
    int node = t / 10, g = t - node * 10;
    int fc0 = g * 4;

    float den[6];
    float4 acc[6];
    float4 fself = *(const float4*)(h2 + (long long)node * 40 + fc0);
#pragma unroll
    for (int h = 0; h < 6; h++) {
        float w = __expf(lrelu(as_[node * 6 + h] + ad_[node * 6 + h]));
        den[h] = w;
        acc[h].x = fself.x * w; acc[h].y = fself.y * w;
        acc[h].z = fself.z * w; acc[h].w = fself.w * w;
    }
    int st = ptr[node], deg = cnt[node];
    int k = 0;
    for (; k + 2 <= deg; k += 2) {
        int slot0 = st + k, slot1 = st + k + 1;
        int s0 = csrc[slot0], s1 = csrc[slot1];
        uint2 raw0 = *(const uint2*)(z + (long long)s0 * 288 + 240 + fc0);
        uint2 raw1 = *(const uint2*)(z + (long long)s1 * 288 + 240 + fc0);
        float2 a01 = __half22float2(*reinterpret_cast<__half2*>(&raw0.x));
        float2 a23 = __half22float2(*reinterpret_cast<__half2*>(&raw0.y));
        float2 b01 = __half22float2(*reinterpret_cast<__half2*>(&raw1.x));
        float2 b23 = __half22float2(*reinterpret_cast<__half2*>(&raw1.y));
        const float* wp0 = &ew[(long long)slot0 * 6];
        const float* wp1 = &ew[(long long)slot1 * 6];
#pragma unroll
        for (int h = 0; h < 6; h++) {
            float w0 = wp0[h], w1 = wp1[h];
            den[h] += w0 + w1;
            acc[h].x += a01.x * w0 + b01.x * w1;
            acc[h].y += a01.y * w0 + b01.y * w1;
            acc[h].z += a23.x * w0 + b23.x * w1;
            acc[h].w += a23.y * w0 + b23.y * w1;
        }
    }
    if (k < deg) {
        int slot = st + k;
        int s = csrc[slot];
        uint2 raw = *(const uint2*)(z + (long long)s * 288 + 240 + fc0);
        float2 f01 = __half22float2(*reinterpret_cast<__half2*>(&raw.x));
        float2 f23 = __half22float2(*reinterpret_cast<__half2*>(&raw.y));
        const float* wp = &ew[(long long)slot * 6];
#pragma unroll
        for (int h = 0; h < 6; h++) {
            float w = wp[h];
            den[h] += w;
            acc[h].x += f01.x * w; acc[h].y += f01.y * w;
            acc[h].z += f23.x * w; acc[h].w += f23.y * w;
        }
    }
#pragma unroll
    for (int h = 0; h < 6; h++) {
        float sc = 1.f / (6.f * den[h]);
        __half2 lo = __floats2half2_rn(acc[h].x * sc, acc[h].y * sc);
        __half2 hi = __floats2half2_rn(acc[h].z * sc, acc[h].w * sc);
        uint2 out;
        out.x = *reinterpret_cast<unsigned*>(&lo);
        out.y = *reinterpret_cast<unsigned*>(&hi);
        *(uint2*)(z + (long long)node * 288 + h * 40 + fc0) = out;
    }
}

// ---------------- host ----------------
extern "C" void kernel_launch(void* const* d_in, const int* in_sizes, int n_in,
                              void* d_out, int out_size) {
    const float* x   = (const float*)d_in[0];
    const int*   ei  = (const int*)d_in[1];
    const float* W1  = (const float*)d_in[2];
    const float* as1 = (const float*)d_in[3];
    const float* ad1 = (const float*)d_in[4];
    const float* b1  = (const float*)d_in[5];
    const float* lw1 = (const float*)d_in[6];
    const float* lb1 = (const float*)d_in[7];
    const float* W2  = (const float*)d_in[8];
    const float* as2 = (const float*)d_in[9];
    const float* ad2 = (const float*)d_in[10];
    const float* b2  = (const float*)d_in[11];
    const float* lw2 = (const float*)d_in[12];
    const float* lb2 = (const float*)d_in[13];
    const float* W3  = (const float*)d_in[14];
    const float* as3 = (const float*)d_in[15];
    const float* ad3 = (const float*)d_in[16];
    const float* b3  = (const float*)d_in[17];
    const float* lw3 = (const float*)d_in[18];
    const float* lb3 = (const float*)d_in[19];
    float* out = (float*)d_out;

    int E = in_sizes[1] / 2;
    int n = in_sizes[0] / 50;
    const int* src = ei;
    const int* dst = ei + E;

    float *xwp, *h, *asrc, *adst, *ew;
    float *w1e, *w2e, *bc1, *bc2, *bc3, *vs3, *vd3;
    __half *w3h, *z;
    int *cnt, *ptr, *cur, *bsum, *csrc;
    cudaGetSymbolAddress((void**)&xwp, g_xwp);
    cudaGetSymbolAddress((void**)&h, g_h);
    cudaGetSymbolAddress((void**)&z, g_z);
    cudaGetSymbolAddress((void**)&asrc, g_asrc);
    cudaGetSymbolAddress((void**)&adst, g_adst);
    cudaGetSymbolAddress((void**)&ew, g_ew);
    cudaGetSymbolAddress((void**)&cnt, g_cnt);
    cudaGetSymbolAddress((void**)&ptr, g_ptr);
    cudaGetSymbolAddress((void**)&cur, g_cur);
    cudaGetSymbolAddress((void**)&bsum, g_bsum);
    cudaGetSymbolAddress((void**)&csrc, g_csrc);
    cudaGetSymbolAddress((void**)&w1e, g_w1e);
    cudaGetSymbolAddress((void**)&w2e, g_w2e);
    cudaGetSymbolAddress((void**)&w3h, g_w3h);
    cudaGetSymbolAddress((void**)&bc1, g_bc1);
    cudaGetSymbolAddress((void**)&bc2, g_bc2);
    cudaGetSymbolAddress((void**)&bc3, g_bc3);
    cudaGetSymbolAddress((void**)&vs3, g_vs3);
    cudaGetSymbolAddress((void**)&vd3, g_vd3);

    // z zero-init (pad cols 280..287 must be zero for the padded GEMM)
    cudaMemsetAsync(z, 0, (size_t)NN * 288 * sizeof(__half));

    // weight repack
    k_repack12<<<cdiv(50 * 88, TPB), TPB>>>(W1, lw1, as1, ad1, b1, lb1, w1e, bc1, 50);
    k_repack12<<<cdiv(40 * 88, TPB), TPB>>>(W2, lw2, as2, ad2, b2, lb2, w2e, bc2, 40);
    k_repack3h<<<cdiv(288 * 128, TPB), TPB>>>(W3, lw3, b3, lb3, w3h, bc3);
    k_vsd3<<<60, TPB>>>(W3, as3, ad3, vs3, vd3);

    // CSR build (shared by all 3 layers)
    cudaMemsetAsync(cnt, 0, (size_t)n * sizeof(int));
    k_hist<<<cdiv(E, TPB), TPB>>>(dst, cnt, E);
    int nb = cdiv(n, 1024);
    k_scan1<<<nb, 1024>>>(cnt, ptr, bsum, n);
    k_scan2<<<1, 128>>>(bsum, nb);
    k_scan3<<<cdiv(n, TPB), TPB>>>(ptr, cur, bsum, n);
    k_scatter<<<cdiv(E, TPB), TPB>>>(src, dst, cur, csrc, E);

    // ---- layer 1 ----
    k_gemm96p<<<cdiv(n, 64), 256>>>(x, 50, w1e, xwp, n, 50);
    k_agg12<<<cdiv(n * 4, TPB), TPB>>>(ptr, cnt, csrc, xwp, bc1, h, nullptr, n);

    // ---- layer 2 ----
    k_gemm96p<<<cdiv(n, 64), 256>>>(h, 40, w2e, xwp, n, 40);
    k_agg12<<<cdiv(n * 4, TPB), TPB>>>(ptr, cnt, csrc, xwp, bc2, h, z, n);

    // ---- layer 3 ----
    k_att3<<<cdiv(n * 6, TPB), TPB>>>(h, vs3, vd3, asrc, adst, n);
    k_exp3<<<cdiv(n * 6, TPB), TPB>>>(ptr, cnt, csrc, asrc, adst, ew, n);
    k_agg3<<<cdiv(n * 10, TPB), TPB>>>(ptr, cnt, csrc, h, ew, asrc, adst, z, n);
    k_gemm_h16<<<cdiv(n, 128), 256>>>(z, w3h, out, 121, n, bc3);
}